// round 1
// baseline (speedup 1.0000x reference)
#include <cuda_runtime.h>
#include <cuda_bf16.h>

#define N_NODES 10000
#define N_EDGES 320000
#define IN_F    256
#define HD      512   // NUM_HEADS * OUT_FEATS
#define NH      8
#define DH      64

// ---------------- scratch (device globals; no allocation allowed) ----------
__device__ float g_ft[N_NODES * HD];        // projected features [N, 512]
__device__ float g_el[N_NODES * NH];
__device__ float g_er[N_NODES * NH];
__device__ int   g_count[N_NODES + 1];
__device__ int   g_rowstart[N_NODES + 1];
__device__ int   g_woff[N_NODES];
__device__ int   g_srcs[N_EDGES];           // src indices sorted by dst (CSR)

// ---------------- 0: zero histogram ----------------
__global__ void k_zero() {
    int i = blockIdx.x * blockDim.x + threadIdx.x;
    if (i <= N_NODES) g_count[i] = 0;
}

// ---------------- 1: GEMM  ft = feat @ W  (fp32 tiled) ----------------
#define BM 64
#define BN 64
#define BK 16
__global__ void k_gemm(const float* __restrict__ A, const float* __restrict__ B) {
    __shared__ float As[BK][BM];   // transposed A tile
    __shared__ float Bs[BK][BN];
    const int bx = blockIdx.x;          // n tile (0..7)
    const int by = blockIdx.y;          // m tile (0..156)
    const int tid = threadIdx.x;        // 256 threads
    const int tr = tid >> 4;            // 0..15
    const int tc = tid & 15;            // 0..15
    const int row0 = by * BM;

    float acc[4][4];
#pragma unroll
    for (int i = 0; i < 4; i++)
#pragma unroll
        for (int j = 0; j < 4; j++) acc[i][j] = 0.f;

    for (int k0 = 0; k0 < IN_F; k0 += BK) {
        // load A tile (64 x 16): 4 floats per thread along k
        {
            int m  = tid >> 2;           // 0..63
            int kq = (tid & 3) * 4;      // 0,4,8,12
            int gm = row0 + m;
            float4 v = make_float4(0.f, 0.f, 0.f, 0.f);
            if (gm < N_NODES) v = *(const float4*)&A[(long long)gm * IN_F + k0 + kq];
            As[kq + 0][m] = v.x; As[kq + 1][m] = v.y;
            As[kq + 2][m] = v.z; As[kq + 3][m] = v.w;
        }
        // load B tile (16 x 64): 4 floats per thread along n
        {
            int kk = tid >> 4;           // 0..15
            int nq = (tid & 15) * 4;     // 0..60
            float4 v = *(const float4*)&B[(long long)(k0 + kk) * HD + bx * BN + nq];
            Bs[kk][nq + 0] = v.x; Bs[kk][nq + 1] = v.y;
            Bs[kk][nq + 2] = v.z; Bs[kk][nq + 3] = v.w;
        }
        __syncthreads();
#pragma unroll
        for (int k = 0; k < BK; k++) {
            float4 a4 = *(const float4*)&As[k][tr * 4];
            float4 b4 = *(const float4*)&Bs[k][tc * 4];
            float a[4] = {a4.x, a4.y, a4.z, a4.w};
            float b[4] = {b4.x, b4.y, b4.z, b4.w};
#pragma unroll
            for (int i = 0; i < 4; i++)
#pragma unroll
                for (int j = 0; j < 4; j++) acc[i][j] += a[i] * b[j];
        }
        __syncthreads();
    }
#pragma unroll
    for (int i = 0; i < 4; i++) {
        int gm = row0 + tr * 4 + i;
        if (gm < N_NODES) {
            float4 v = make_float4(acc[i][0], acc[i][1], acc[i][2], acc[i][3]);
            *(float4*)&g_ft[(long long)gm * HD + bx * BN + tc * 4] = v;
        }
    }
}

// ---------------- 2: per-node attention logits el, er ----------------
// one warp per (node, head)
__global__ void k_elr(const float* __restrict__ al, const float* __restrict__ ar) {
    int gw   = blockIdx.x * 8 + (threadIdx.x >> 5);  // 0..79999
    int lane = threadIdx.x & 31;
    int n = gw >> 3, h = gw & 7;
    const float* f = &g_ft[(long long)n * HD + h * DH];
    float f0 = f[lane], f1 = f[lane + 32];
    float sl = f0 * al[h * DH + lane] + f1 * al[h * DH + lane + 32];
    float sr = f0 * ar[h * DH + lane] + f1 * ar[h * DH + lane + 32];
#pragma unroll
    for (int o = 16; o > 0; o >>= 1) {
        sl += __shfl_xor_sync(0xffffffffu, sl, o);
        sr += __shfl_xor_sync(0xffffffffu, sr, o);
    }
    if (lane == 0) {
        g_el[n * NH + h] = sl;
        g_er[n * NH + h] = sr;
    }
}

// ---------------- 3: degree histogram ----------------
__global__ void k_hist(const int* __restrict__ dst) {
    int e = blockIdx.x * blockDim.x + threadIdx.x;
    atomicAdd(&g_count[dst[e]], 1);
}

// ---------------- 4: exclusive scan (single block) ----------------
__global__ void k_scan() {
    __shared__ int partial[1024];
    int tid = threadIdx.x;
    int base = tid * 10;   // 1024*10 >= 10000
    int local[10];
    int s = 0;
#pragma unroll
    for (int i = 0; i < 10; i++) {
        int idx = base + i;
        int c = (idx < N_NODES) ? g_count[idx] : 0;
        local[i] = s;
        s += c;
    }
    partial[tid] = s;
    __syncthreads();
    for (int off = 1; off < 1024; off <<= 1) {
        int v = 0;
        if (tid >= off) v = partial[tid - off];
        __syncthreads();
        if (tid >= off) partial[tid] += v;
        __syncthreads();
    }
    int excl = (tid == 0) ? 0 : partial[tid - 1];
#pragma unroll
    for (int i = 0; i < 10; i++) {
        int idx = base + i;
        if (idx < N_NODES) {
            g_rowstart[idx] = excl + local[i];
            g_woff[idx]     = excl + local[i];
        }
    }
    if (tid == 1023) g_rowstart[N_NODES] = partial[1023];
}

// ---------------- 5: scatter edges into CSR buckets ----------------
__global__ void k_scatter(const int* __restrict__ src, const int* __restrict__ dst) {
    int e = blockIdx.x * blockDim.x + threadIdx.x;
    int p = atomicAdd(&g_woff[dst[e]], 1);
    g_srcs[p] = src[e];
}

// ---------------- 6: per-dst softmax + aggregation (warp per dst) ----------
__global__ void k_agg(const float* __restrict__ adj, const int* __restrict__ idxp,
                      float* __restrict__ out) {
    int gw   = blockIdx.x * (blockDim.x >> 5) + (threadIdx.x >> 5);  // dst node
    int lane = threadIdx.x & 31;
    int d = gw;
    int s0 = g_rowstart[d], s1 = g_rowstart[d + 1];

    float4 acc[4];
#pragma unroll
    for (int k = 0; k < 4; k++) acc[k] = make_float4(0.f, 0.f, 0.f, 0.f);

    if (s1 > s0) {
        long long idx = (long long)(*idxp);
        int h   = lane & 7;
        int sub = lane >> 3;
        float er_h = g_er[d * NH + h];

        // pass 1: per-head max of leakyrelu(el[src]+er[dst])
        float m = -3.0e38f;
        for (int j = s0 + sub; j < s1; j += 4) {
            int s = g_srcs[j];
            float e = g_el[s * NH + h] + er_h;
            e = e > 0.f ? e : 0.2f * e;
            m = fmaxf(m, e);
        }
        m = fmaxf(m, __shfl_xor_sync(0xffffffffu, m, 8));
        m = fmaxf(m, __shfl_xor_sync(0xffffffffu, m, 16));

        // pass 2: per-head sum of exp
        float ssum = 0.f;
        for (int j = s0 + sub; j < s1; j += 4) {
            int s = g_srcs[j];
            float e = g_el[s * NH + h] + er_h;
            e = e > 0.f ? e : 0.2f * e;
            ssum += __expf(e - m);
        }
        ssum += __shfl_xor_sync(0xffffffffu, ssum, 8);
        ssum += __shfl_xor_sync(0xffffffffu, ssum, 16);
        float inv = __frcp_rn(ssum);

        // pass 3: accumulate a * ft[src]
        const long long adjbase = idx * (long long)N_NODES + (long long)d + idx;
        for (int j = s0; j < s1; j++) {
            int s = g_srcs[j];
            float e = g_el[s * NH + h] + er_h;
            e = e > 0.f ? e : 0.2f * e;
            float w = __ldg(&adj[(long long)s * N_NODES + adjbase]);
            float a = __expf(e - m) * inv * w;   // valid for head (lane&7) on every lane
            const float4* f4 = (const float4*)&g_ft[(long long)s * HD];
#pragma unroll
            for (int k = 0; k < 4; k++) {
                // element block k covers features [128k, 128k+128): head = 2k + (lane>=16)
                float ah = __shfl_sync(0xffffffffu, a, 2 * k + (lane >> 4));
                float4 v = __ldg(&f4[k * 32 + lane]);
                acc[k].x += ah * v.x; acc[k].y += ah * v.y;
                acc[k].z += ah * v.z; acc[k].w += ah * v.w;
            }
        }
    }
    float4* o4 = (float4*)(out + (long long)d * HD);
#pragma unroll
    for (int k = 0; k < 4; k++) o4[k * 32 + lane] = acc[k];
}

// ---------------- launch ----------------
extern "C" void kernel_launch(void* const* d_in, const int* in_sizes, int n_in,
                              void* d_out, int out_size) {
    const float* feat = (const float*)d_in[0];
    const float* W    = (const float*)d_in[1];
    const float* al   = (const float*)d_in[2];
    const float* ar   = (const float*)d_in[3];
    const float* adj  = (const float*)d_in[4];
    const int*   src  = (const int*)d_in[5];
    const int*   dst  = (const int*)d_in[6];
    const int*   idxp = (const int*)d_in[7];
    float* out = (float*)d_out;

    k_zero<<<(N_NODES + 256) / 256, 256>>>();
    dim3 ggrid(HD / BN, (N_NODES + BM - 1) / BM);
    k_gemm<<<ggrid, 256>>>(feat, W);
    k_elr<<<N_NODES, 256>>>(al, ar);                 // 10000 blocks x 8 warps = 80000 (n,h)
    k_hist<<<N_EDGES / 256, 256>>>(dst);
    k_scan<<<1, 1024>>>();
    k_scatter<<<N_EDGES / 256, 256>>>(src, dst);
    k_agg<<<N_NODES / 8, 256>>>(adj, idxp, out);     // warp per dst node
}

// round 2
// speedup vs baseline: 1.2311x; 1.2311x over previous
#include <cuda_runtime.h>
#include <cuda_bf16.h>
#include <cuda_fp16.h>

#define N_NODES 10000
#define N_EDGES 320000
#define IN_F    256
#define HD      512   // NUM_HEADS * OUT_FEATS
#define NH      8
#define DH      64

// ---------------- scratch (device globals; no allocation allowed) ----------
__device__ __half g_fth[N_NODES * HD];      // projected features, fp16 [N, 512]
__device__ float  g_el[N_NODES * NH];
__device__ float  g_er[N_NODES * NH];
__device__ int    g_count[N_NODES + 1];
__device__ int    g_rowstart[N_NODES + 1];
__device__ int    g_woff[N_NODES];
__device__ int    g_srcs[N_EDGES];          // src indices bucketed by dst (CSR)

// ---------------- 0: zero histogram ----------------
__global__ void k_zero() {
    int i = blockIdx.x * blockDim.x + threadIdx.x;
    if (i <= N_NODES) g_count[i] = 0;
}

// ---------------- 1: GEMM ft = feat @ W  (+ fused el/er, fp16 ft store) ----
#define BM 128
#define BN 64
#define BK 16
__global__ void k_gemm(const float* __restrict__ A, const float* __restrict__ B,
                       const float* __restrict__ al, const float* __restrict__ ar) {
    __shared__ float As[BK][BM];
    __shared__ float Bs[BK][BN];
    const int bx = blockIdx.x;           // n tile == head (0..7)
    const int by = blockIdx.y;           // m tile (0..78)
    const int tid = threadIdx.x;         // 256 threads
    const int tr = tid >> 4;             // 0..15  (row group: 8 rows)
    const int tc = tid & 15;             // 0..15  (col group: 4 cols)
    const int row0 = by * BM;

    float acc[8][4];
#pragma unroll
    for (int i = 0; i < 8; i++)
#pragma unroll
        for (int j = 0; j < 4; j++) acc[i][j] = 0.f;

    const int lm   = tid >> 1;           // 0..127 (A-load row)
    const int lk   = (tid & 1) * 8;      // 0 or 8 (A-load k offset)
    const int gm_l = row0 + lm;
    const int bkk  = tid >> 4;           // 0..15  (B-load k)
    const int bnq  = (tid & 15) * 4;     // 0..60  (B-load n)

    for (int k0 = 0; k0 < IN_F; k0 += BK) {
        float4 a0 = make_float4(0.f, 0.f, 0.f, 0.f);
        float4 a1 = make_float4(0.f, 0.f, 0.f, 0.f);
        if (gm_l < N_NODES) {
            const float* ap = &A[(long long)gm_l * IN_F + k0 + lk];
            a0 = *(const float4*)ap;
            a1 = *(const float4*)(ap + 4);
        }
        float4 bv = *(const float4*)&B[(long long)(k0 + bkk) * HD + bx * BN + bnq];
        __syncthreads();
        As[lk + 0][lm] = a0.x; As[lk + 1][lm] = a0.y;
        As[lk + 2][lm] = a0.z; As[lk + 3][lm] = a0.w;
        As[lk + 4][lm] = a1.x; As[lk + 5][lm] = a1.y;
        As[lk + 6][lm] = a1.z; As[lk + 7][lm] = a1.w;
        Bs[bkk][bnq + 0] = bv.x; Bs[bkk][bnq + 1] = bv.y;
        Bs[bkk][bnq + 2] = bv.z; Bs[bkk][bnq + 3] = bv.w;
        __syncthreads();
#pragma unroll
        for (int k = 0; k < BK; k++) {
            float4 x0 = *(const float4*)&As[k][tr * 8];
            float4 x1 = *(const float4*)&As[k][tr * 8 + 4];
            float4 y  = *(const float4*)&Bs[k][tc * 4];
            float xs[8] = {x0.x, x0.y, x0.z, x0.w, x1.x, x1.y, x1.z, x1.w};
            float ys[4] = {y.x, y.y, y.z, y.w};
#pragma unroll
            for (int i = 0; i < 8; i++)
#pragma unroll
                for (int j = 0; j < 4; j++) acc[i][j] += xs[i] * ys[j];
        }
    }

    // epilogue: fp16 ft store + fused el/er (this block owns full head bx)
    float4 al4 = *(const float4*)&al[bx * 64 + tc * 4];
    float4 ar4 = *(const float4*)&ar[bx * 64 + tc * 4];
#pragma unroll
    for (int i = 0; i < 8; i++) {
        int gm = row0 + tr * 8 + i;
        float4 v = make_float4(acc[i][0], acc[i][1], acc[i][2], acc[i][3]);
        float el = v.x * al4.x + v.y * al4.y + v.z * al4.z + v.w * al4.w;
        float er = v.x * ar4.x + v.y * ar4.y + v.z * ar4.z + v.w * ar4.w;
#pragma unroll
        for (int off = 8; off >= 1; off >>= 1) {
            el += __shfl_xor_sync(0xffffffffu, el, off);
            er += __shfl_xor_sync(0xffffffffu, er, off);
        }
        if (gm < N_NODES) {
            __half2* hp = (__half2*)&g_fth[(long long)gm * HD + bx * 64 + tc * 4];
            hp[0] = __floats2half2_rn(v.x, v.y);
            hp[1] = __floats2half2_rn(v.z, v.w);
            if (tc == 0) {
                g_el[gm * NH + bx] = el;
                g_er[gm * NH + bx] = er;
            }
        }
    }
}

// ---------------- 2: degree histogram ----------------
__global__ void k_hist(const int* __restrict__ dst) {
    int e = blockIdx.x * blockDim.x + threadIdx.x;
    atomicAdd(&g_count[dst[e]], 1);
}

// ---------------- 3: exclusive scan (single block, warp-shuffle) ----------
__global__ void k_scan() {
    __shared__ int wsums[32];
    int tid = threadIdx.x, lane = tid & 31, w = tid >> 5;
    int base = tid * 10;   // 1024*10 >= 10000
    int local[10];
    int s = 0;
#pragma unroll
    for (int i = 0; i < 10; i++) {
        int idx = base + i;
        int c = (idx < N_NODES) ? g_count[idx] : 0;
        local[i] = s;
        s += c;
    }
    int inc = s;
#pragma unroll
    for (int off = 1; off < 32; off <<= 1) {
        int v = __shfl_up_sync(0xffffffffu, inc, off);
        if (lane >= off) inc += v;
    }
    if (lane == 31) wsums[w] = inc;
    __syncthreads();
    if (w == 0) {
        int v = wsums[lane];
        int wi = v;
#pragma unroll
        for (int off = 1; off < 32; off <<= 1) {
            int t = __shfl_up_sync(0xffffffffu, wi, off);
            if (lane >= off) wi += t;
        }
        wsums[lane] = wi - v;   // exclusive
    }
    __syncthreads();
    int excl = wsums[w] + inc - s;
#pragma unroll
    for (int i = 0; i < 10; i++) {
        int idx = base + i;
        if (idx < N_NODES) {
            g_rowstart[idx] = excl + local[i];
            g_woff[idx]     = excl + local[i];
        }
    }
    if (tid == 1023) g_rowstart[N_NODES] = excl + s;
}

// ---------------- 4: scatter edges into CSR buckets ----------------
__global__ void k_scatter(const int* __restrict__ src, const int* __restrict__ dst) {
    int e = blockIdx.x * blockDim.x + threadIdx.x;
    int p = atomicAdd(&g_woff[dst[e]], 1);
    g_srcs[p] = src[e];
}

// ---------------- 5: per-dst softmax + aggregation (warp per dst) ----------
__global__ void k_agg(const float* __restrict__ adj, const int* __restrict__ idxp,
                      float* __restrict__ out) {
    int d    = blockIdx.x * 8 + (threadIdx.x >> 5);
    int lane = threadIdx.x & 31;
    int s0 = g_rowstart[d], s1 = g_rowstart[d + 1];

    float acc0[8], acc1[8];
#pragma unroll
    for (int t = 0; t < 8; t++) { acc0[t] = 0.f; acc1[t] = 0.f; }

    if (s1 > s0) {
        int idx = *idxp;
        int h   = lane & 7;
        int sub = lane >> 3;
        float er_h = g_er[d * NH + h];

        // online per-head max + expsum (strided across 4 sub-lanes)
        float m = -1e30f, ssum = 0.f;
        for (int j = s0 + sub; j < s1; j += 4) {
            int s = g_srcs[j];
            float e = g_el[s * NH + h] + er_h;
            e = e > 0.f ? e : 0.2f * e;
            if (e > m) { ssum *= __expf(m - e); m = e; }
            ssum += __expf(e - m);
        }
#pragma unroll
        for (int off = 8; off <= 16; off <<= 1) {
            float mo = __shfl_xor_sync(0xffffffffu, m, off);
            float so = __shfl_xor_sync(0xffffffffu, ssum, off);
            float mn = fmaxf(m, mo);
            ssum = ssum * __expf(m - mn) + so * __expf(mo - mn);
            m = mn;
        }
        float inv = __frcp_rn(ssum);

        const long long adjbase = (long long)idx * N_NODES + (long long)d + idx;
        const int q0 = lane >> 3;        // head for fp16 chunk 0 (features lane*8..)
        const int q1 = 4 + (lane >> 3);  // head for fp16 chunk 1 (features 256+lane*8..)
        for (int j = s0; j < s1; j++) {
            int s = g_srcs[j];
            float e = g_el[s * NH + h] + er_h;
            e = e > 0.f ? e : 0.2f * e;
            float wadj = __ldg(&adj[(long long)s * N_NODES + adjbase]);
            float a = __expf(e - m) * inv * wadj;     // head h value on lane
            float a0 = __shfl_sync(0xffffffffu, a, q0);
            float a1 = __shfl_sync(0xffffffffu, a, q1);
            const uint4* fh = (const uint4*)&g_fth[(long long)s * HD];
            uint4 u0 = __ldg(&fh[lane]);
            uint4 u1 = __ldg(&fh[lane + 32]);
            {
                const __half2* hp = (const __half2*)&u0;
#pragma unroll
                for (int t = 0; t < 4; t++) {
                    float2 f = __half22float2(hp[t]);
                    acc0[2 * t]     += a0 * f.x;
                    acc0[2 * t + 1] += a0 * f.y;
                }
            }
            {
                const __half2* hp = (const __half2*)&u1;
#pragma unroll
                for (int t = 0; t < 4; t++) {
                    float2 f = __half22float2(hp[t]);
                    acc1[2 * t]     += a1 * f.x;
                    acc1[2 * t + 1] += a1 * f.y;
                }
            }
        }
    }
    float* o = out + (long long)d * HD;
    *(float4*)&o[lane * 8]           = make_float4(acc0[0], acc0[1], acc0[2], acc0[3]);
    *(float4*)&o[lane * 8 + 4]       = make_float4(acc0[4], acc0[5], acc0[6], acc0[7]);
    *(float4*)&o[256 + lane * 8]     = make_float4(acc1[0], acc1[1], acc1[2], acc1[3]);
    *(float4*)&o[256 + lane * 8 + 4] = make_float4(acc1[4], acc1[5], acc1[6], acc1[7]);
}

// ---------------- launch ----------------
extern "C" void kernel_launch(void* const* d_in, const int* in_sizes, int n_in,
                              void* d_out, int out_size) {
    const float* feat = (const float*)d_in[0];
    const float* W    = (const float*)d_in[1];
    const float* al   = (const float*)d_in[2];
    const float* ar   = (const float*)d_in[3];
    const float* adj  = (const float*)d_in[4];
    const int*   src  = (const int*)d_in[5];
    const int*   dst  = (const int*)d_in[6];
    const int*   idxp = (const int*)d_in[7];
    float* out = (float*)d_out;

    k_zero<<<(N_NODES + 256) / 256, 256>>>();
    dim3 ggrid(HD / BN, (N_NODES + BM - 1) / BM);
    k_gemm<<<ggrid, 256>>>(feat, W, al, ar);
    k_hist<<<N_EDGES / 256, 256>>>(dst);
    k_scan<<<1, 1024>>>();
    k_scatter<<<N_EDGES / 256, 256>>>(src, dst);
    k_agg<<<N_NODES / 8, 256>>>(adj, idxp, out);
}

// round 5
// speedup vs baseline: 1.7296x; 1.4049x over previous
#include <cuda_runtime.h>
#include <cuda_fp16.h>
#include <cstdint>

#define N_NODES 10000
#define N_EDGES 320000
#define IN_F    256
#define HD      512   // NUM_HEADS * OUT_FEATS
#define NH      8

// ---------------- scratch (device globals; no allocation allowed) ----------
__device__ __half g_fth[N_NODES * HD];      // projected features fp16 [N, 512]
__device__ float  g_el[N_NODES * NH];
__device__ float  g_er[N_NODES * NH];
__device__ int    g_count[10240];           // padded for int4 access
__device__ int    g_rowstart[N_NODES + 1];
__device__ int    g_woff[N_NODES];
__device__ int    g_srcs[N_EDGES];          // src indices bucketed by dst (CSR)

// ---------------- mma / ldmatrix helpers ----------------
__device__ __forceinline__ void ldsm_x4(unsigned* r, unsigned addr) {
    asm volatile("ldmatrix.sync.aligned.m8n8.x4.shared.b16 {%0,%1,%2,%3}, [%4];"
                 : "=r"(r[0]), "=r"(r[1]), "=r"(r[2]), "=r"(r[3]) : "r"(addr));
}
__device__ __forceinline__ void ldsm_x4t(unsigned* r, unsigned addr) {
    asm volatile("ldmatrix.sync.aligned.m8n8.x4.trans.shared.b16 {%0,%1,%2,%3}, [%4];"
                 : "=r"(r[0]), "=r"(r[1]), "=r"(r[2]), "=r"(r[3]) : "r"(addr));
}
__device__ __forceinline__ void mma16816(float* c, const unsigned* a, const unsigned* b) {
    asm volatile("mma.sync.aligned.m16n8k16.row.col.f32.f16.f16.f32 "
                 "{%0,%1,%2,%3}, {%4,%5,%6,%7}, {%8,%9}, {%0,%1,%2,%3};"
                 : "+f"(c[0]), "+f"(c[1]), "+f"(c[2]), "+f"(c[3])
                 : "r"(a[0]), "r"(a[1]), "r"(a[2]), "r"(a[3]), "r"(b[0]), "r"(b[1]));
}

// ---------------- 0: zero histogram ----------------
__global__ void k_zero() {
    int i = blockIdx.x * blockDim.x + threadIdx.x;
    if (i < 10240) g_count[i] = 0;
}

// ---------------- 1: tensor-core GEMM ft = feat @ W (+ fused el/er) --------
// block: 256 threads = 8 warps. Tile: 128 rows x 64 cols (one head). K = 256.
// warp w owns rows [w*16, w*16+16) x all 64 cols: 1 m-atom x 8 n-atoms.
#define ASTRIDE 72
__global__ __launch_bounds__(256) void k_gemm(const float* __restrict__ A,
                                              const float* __restrict__ B,
                                              const float* __restrict__ al,
                                              const float* __restrict__ ar) {
    __shared__ __half As[128 * ASTRIDE];
    __shared__ __half Bs[64 * ASTRIDE];
    const int bx = blockIdx.x;          // head (0..7)
    const int by = blockIdx.y;          // row tile (0..78)
    const int tid = threadIdx.x;
    const int w = tid >> 5, lane = tid & 31;

    float acc[8][4];
#pragma unroll
    for (int i = 0; i < 8; i++)
#pragma unroll
        for (int j = 0; j < 4; j++) acc[i][j] = 0.f;

    const int arow = tid >> 1, apart = tid & 1;   // A staging: row, 32-col half
    const int gm_l = by * 128 + arow;
    const bool aok = gm_l < N_NODES;
    const int bk = tid >> 2, bnq = (tid & 3) * 16; // B staging: k row, 16-col quarter

    const unsigned s_as = (unsigned)__cvta_generic_to_shared(As);
    const unsigned s_bs = (unsigned)__cvta_generic_to_shared(Bs);
    const int r15 = lane & 15, c8 = (lane >> 4) * 8;
    const unsigned a_base = s_as + (unsigned)(((w * 16 + r15) * ASTRIDE + c8) * 2);
    const unsigned b_base = s_bs + (unsigned)((r15 * ASTRIDE + c8) * 2);

    for (int kc = 0; kc < 4; kc++) {      // K chunks of 64
        float4 av[8];
        const float* ap = A + (long long)gm_l * IN_F + kc * 64 + apart * 32;
#pragma unroll
        for (int j = 0; j < 8; j++)
            av[j] = aok ? *(const float4*)(ap + j * 4) : make_float4(0.f, 0.f, 0.f, 0.f);
        float4 bv[4];
        const float* bp = B + (long long)(kc * 64 + bk) * HD + bx * 64 + bnq;
#pragma unroll
        for (int j = 0; j < 4; j++) bv[j] = *(const float4*)(bp + j * 4);
        __syncthreads();
        __half* asr = &As[arow * ASTRIDE + apart * 32];
#pragma unroll
        for (int j = 0; j < 8; j++) {
            *(__half2*)(asr + j * 4)     = __floats2half2_rn(av[j].x, av[j].y);
            *(__half2*)(asr + j * 4 + 2) = __floats2half2_rn(av[j].z, av[j].w);
        }
        __half* bsr = &Bs[bk * ASTRIDE + bnq];
#pragma unroll
        for (int j = 0; j < 4; j++) {
            *(__half2*)(bsr + j * 4)     = __floats2half2_rn(bv[j].x, bv[j].y);
            *(__half2*)(bsr + j * 4 + 2) = __floats2half2_rn(bv[j].z, bv[j].w);
        }
        __syncthreads();
#pragma unroll
        for (int ks = 0; ks < 4; ks++) {  // k16 steps
            unsigned af[4];
            ldsm_x4(af, a_base + ks * 32);
#pragma unroll
            for (int nb = 0; nb < 4; nb++) {
                unsigned bf[4];
                ldsm_x4t(bf, b_base + (unsigned)(ks * 16 * ASTRIDE * 2) + nb * 32);
                mma16816(acc[nb * 2],     af, bf);
                mma16816(acc[nb * 2 + 1], af, bf + 2);
            }
        }
    }

    // epilogue: fused el/er + fp16 ft store
    const int g = lane >> 2, tg = lane & 3;
    const int row0 = by * 128 + w * 16 + g;
    const int row1 = row0 + 8;
    float el0 = 0.f, er0 = 0.f, el1 = 0.f, er1 = 0.f;
#pragma unroll
    for (int na = 0; na < 8; na++) {
        int n = bx * 64 + na * 8 + tg * 2;
        float a0 = al[n], a1 = al[n + 1];
        float r0 = ar[n], r1 = ar[n + 1];
        el0 += acc[na][0] * a0 + acc[na][1] * a1;
        er0 += acc[na][0] * r0 + acc[na][1] * r1;
        el1 += acc[na][2] * a0 + acc[na][3] * a1;
        er1 += acc[na][2] * r0 + acc[na][3] * r1;
    }
#pragma unroll
    for (int off = 1; off <= 2; off <<= 1) {
        el0 += __shfl_xor_sync(0xffffffffu, el0, off);
        er0 += __shfl_xor_sync(0xffffffffu, er0, off);
        el1 += __shfl_xor_sync(0xffffffffu, el1, off);
        er1 += __shfl_xor_sync(0xffffffffu, er1, off);
    }
    if (row0 < N_NODES) {
        __half* fo = &g_fth[(long long)row0 * HD + bx * 64 + tg * 2];
#pragma unroll
        for (int na = 0; na < 8; na++)
            *(__half2*)(fo + na * 8) = __floats2half2_rn(acc[na][0], acc[na][1]);
        if (tg == 0) { g_el[row0 * NH + bx] = el0; g_er[row0 * NH + bx] = er0; }
    }
    if (row1 < N_NODES) {
        __half* fo = &g_fth[(long long)row1 * HD + bx * 64 + tg * 2];
#pragma unroll
        for (int na = 0; na < 8; na++)
            *(__half2*)(fo + na * 8) = __floats2half2_rn(acc[na][2], acc[na][3]);
        if (tg == 0) { g_el[row1 * NH + bx] = el1; g_er[row1 * NH + bx] = er1; }
    }
}

// ---------------- 2: degree histogram (int4) ----------------
__global__ void k_hist(const int4* __restrict__ dst4) {
    int i = blockIdx.x * blockDim.x + threadIdx.x;
    if (i < N_EDGES / 4) {
        int4 d = dst4[i];
        atomicAdd(&g_count[d.x], 1);
        atomicAdd(&g_count[d.y], 1);
        atomicAdd(&g_count[d.z], 1);
        atomicAdd(&g_count[d.w], 1);
    }
}

// ---------------- 3: exclusive scan (single block, smem-staged) ------------
__global__ void k_scan() {
    __shared__ int sh[10240];
    __shared__ int wsums[32];
    int tid = threadIdx.x, lane = tid & 31, w = tid >> 5;
    int4* sh4 = (int4*)sh;
    const int4* gc4 = (const int4*)g_count;
    for (int i = tid; i < 2560; i += 1024) sh4[i] = gc4[i];
    __syncthreads();
    int base = tid * 10;
    int local[10];
    int s = 0;
#pragma unroll
    for (int i = 0; i < 10; i++) { local[i] = s; s += sh[base + i]; }
    int inc = s;
#pragma unroll
    for (int off = 1; off < 32; off <<= 1) {
        int v = __shfl_up_sync(0xffffffffu, inc, off);
        if (lane >= off) inc += v;
    }
    if (lane == 31) wsums[w] = inc;
    __syncthreads();
    if (w == 0) {
        int v = wsums[lane];
        int wi = v;
#pragma unroll
        for (int off = 1; off < 32; off <<= 1) {
            int t = __shfl_up_sync(0xffffffffu, wi, off);
            if (lane >= off) wi += t;
        }
        wsums[lane] = wi - v;   // exclusive
    }
    __syncthreads();
    int excl = wsums[w] + inc - s;
#pragma unroll
    for (int i = 0; i < 10; i++) sh[base + i] = excl + local[i];
    __syncthreads();
    int4* rs4 = (int4*)g_rowstart;
    int4* wo4 = (int4*)g_woff;
    for (int i = tid; i < 2500; i += 1024) { int4 v = sh4[i]; rs4[i] = v; wo4[i] = v; }
    if (tid == 0) g_rowstart[N_NODES] = N_EDGES;
}

// ---------------- 4: scatter edges into CSR buckets (int4) ----------------
__global__ void k_scatter(const int4* __restrict__ src4, const int4* __restrict__ dst4) {
    int i = blockIdx.x * blockDim.x + threadIdx.x;
    if (i < N_EDGES / 4) {
        int4 d = dst4[i];
        int4 s = src4[i];
        g_srcs[atomicAdd(&g_woff[d.x], 1)] = s.x;
        g_srcs[atomicAdd(&g_woff[d.y], 1)] = s.y;
        g_srcs[atomicAdd(&g_woff[d.z], 1)] = s.z;
        g_srcs[atomicAdd(&g_woff[d.w], 1)] = s.w;
    }
}

// ---------------- 5: per-dst softmax + aggregation (warp per dst) ----------
__global__ void k_agg(const float* __restrict__ adj, const int* __restrict__ idxp,
                      float* __restrict__ out) {
    int d    = blockIdx.x * 8 + (threadIdx.x >> 5);
    int lane = threadIdx.x & 31;
    int s0 = g_rowstart[d], s1 = g_rowstart[d + 1];

    float acc0[8], acc1[8];
#pragma unroll
    for (int t = 0; t < 8; t++) { acc0[t] = 0.f; acc1[t] = 0.f; }

    if (s1 > s0) {
        int idx = *idxp;
        int h   = lane & 7;
        int sub = lane >> 3;
        float er_h = g_er[d * NH + h];

        // online per-head max + expsum (strided across 4 sub-lanes)
        float m = -1e30f, ssum = 0.f;
        for (int j = s0 + sub; j < s1; j += 4) {
            int s = g_srcs[j];
            float e = g_el[s * NH + h] + er_h;
            e = e > 0.f ? e : 0.2f * e;
            if (e > m) { ssum *= __expf(m - e); m = e; }
            ssum += __expf(e - m);
        }
#pragma unroll
        for (int off = 8; off <= 16; off <<= 1) {
            float mo = __shfl_xor_sync(0xffffffffu, m, off);
            float so = __shfl_xor_sync(0xffffffffu, ssum, off);
            float mn = fmaxf(m, mo);
            ssum = ssum * __expf(m - mn) + so * __expf(mo - mn);
            m = mn;
        }
        float inv = __frcp_rn(ssum);

        const long long adjbase = (long long)idx * N_NODES + (long long)d + idx;
        const int q0 = lane >> 3;        // head for fp16 chunk 0
        const int q1 = 4 + (lane >> 3);  // head for fp16 chunk 1
#pragma unroll 2
        for (int j = s0; j < s1; j++) {
            int s = g_srcs[j];
            float e = g_el[s * NH + h] + er_h;
            e = e > 0.f ? e : 0.2f * e;
            float wadj = __ldg(&adj[(long long)s * N_NODES + adjbase]);
            float a = __expf(e - m) * inv * wadj;
            float a0 = __shfl_sync(0xffffffffu, a, q0);
            float a1 = __shfl_sync(0xffffffffu, a, q1);
            const uint4* fh = (const uint4*)&g_fth[(long long)s * HD];
            uint4 u0 = __ldg(&fh[lane]);
            uint4 u1 = __ldg(&fh[lane + 32]);
            {
                const __half2* hp = (const __half2*)&u0;
#pragma unroll
                for (int t = 0; t < 4; t++) {
                    float2 f = __half22float2(hp[t]);
                    acc0[2 * t]     += a0 * f.x;
                    acc0[2 * t + 1] += a0 * f.y;
                }
            }
            {
                const __half2* hp = (const __half2*)&u1;
#pragma unroll
                for (int t = 0; t < 4; t++) {
                    float2 f = __half22float2(hp[t]);
                    acc1[2 * t]     += a1 * f.x;
                    acc1[2 * t + 1] += a1 * f.y;
                }
            }
        }
    }
    float* o = out + (long long)d * HD;
    *(float4*)&o[lane * 8]           = make_float4(acc0[0], acc0[1], acc0[2], acc0[3]);
    *(float4*)&o[lane * 8 + 4]       = make_float4(acc0[4], acc0[5], acc0[6], acc0[7]);
    *(float4*)&o[256 + lane * 8]     = make_float4(acc1[0], acc1[1], acc1[2], acc1[3]);
    *(float4*)&o[256 + lane * 8 + 4] = make_float4(acc1[4], acc1[5], acc1[6], acc1[7]);
}

// ---------------- streams for fork-join overlap (static init; no device mem)
static cudaStream_t g_s2;
static cudaEvent_t  g_evA, g_evB;
namespace {
struct StreamInit {
    StreamInit() {
        cudaStreamCreateWithFlags(&g_s2, cudaStreamNonBlocking);
        cudaEventCreateWithFlags(&g_evA, cudaEventDisableTiming);
        cudaEventCreateWithFlags(&g_evB, cudaEventDisableTiming);
    }
};
StreamInit s_streamInit;
}

// ---------------- launch ----------------
extern "C" void kernel_launch(void* const* d_in, const int* in_sizes, int n_in,
                              void* d_out, int out_size) {
    const float* feat = (const float*)d_in[0];
    const float* W    = (const float*)d_in[1];
    const float* al   = (const float*)d_in[2];
    const float* ar   = (const float*)d_in[3];
    const float* adj  = (const float*)d_in[4];
    const int*   src  = (const int*)d_in[5];
    const int*   dst  = (const int*)d_in[6];
    const int*   idxp = (const int*)d_in[7];
    float* out = (float*)d_out;

    // fork: CSR-build chain on g_s2, GEMM on capture (default) stream
    cudaEventRecord(g_evA, 0);
    cudaStreamWaitEvent(g_s2, g_evA, 0);

    k_zero<<<40, 256, 0, g_s2>>>();
    k_hist<<<(N_EDGES / 4 + 255) / 256, 256, 0, g_s2>>>((const int4*)dst);
    k_scan<<<1, 1024, 0, g_s2>>>();
    k_scatter<<<(N_EDGES / 4 + 255) / 256, 256, 0, g_s2>>>((const int4*)src, (const int4*)dst);
    cudaEventRecord(g_evB, g_s2);

    dim3 ggrid(NH, (N_NODES + 127) / 128);
    k_gemm<<<ggrid, 256>>>(feat, W, al, ar);

    // join, then aggregate
    cudaStreamWaitEvent(0, g_evB, 0);
    k_agg<<<N_NODES / 8, 256>>>(adj, idxp, out);
}

// round 9
// speedup vs baseline: 1.8961x; 1.0962x over previous
#include <cuda_runtime.h>
#include <cuda_fp16.h>
#include <cstdint>

#define N_NODES 10000
#define N_EDGES 320000
#define IN_F    256
#define HD      512   // NUM_HEADS * OUT_FEATS
#define NH      8

// ---------------- scratch (device globals; zero-initialized at load) -------
__device__ __half g_fth[N_NODES * HD];      // projected features fp16 [N, 512]
__device__ float  g_el[N_NODES * NH];
__device__ float  g_er[N_NODES * NH];
__device__ int    g_count[10240];           // zeroed by k_scan after use
__device__ int    g_rowstart[N_NODES + 1];
__device__ int    g_woff[N_NODES];
__device__ int    g_srcs[N_EDGES];          // src indices bucketed by dst (CSR)
__device__ float  g_a[N_EDGES * NH];        // normalized attention (incl adj mask)

// ---------------- mma / ldmatrix helpers ----------------
__device__ __forceinline__ void ldsm_x4(unsigned* r, unsigned addr) {
    asm volatile("ldmatrix.sync.aligned.m8n8.x4.shared.b16 {%0,%1,%2,%3}, [%4];"
                 : "=r"(r[0]), "=r"(r[1]), "=r"(r[2]), "=r"(r[3]) : "r"(addr));
}
__device__ __forceinline__ void ldsm_x4t(unsigned* r, unsigned addr) {
    asm volatile("ldmatrix.sync.aligned.m8n8.x4.trans.shared.b16 {%0,%1,%2,%3}, [%4];"
                 : "=r"(r[0]), "=r"(r[1]), "=r"(r[2]), "=r"(r[3]) : "r"(addr));
}
__device__ __forceinline__ void mma16816(float* c, const unsigned* a, const unsigned* b) {
    asm volatile("mma.sync.aligned.m16n8k16.row.col.f32.f16.f16.f32 "
                 "{%0,%1,%2,%3}, {%4,%5,%6,%7}, {%8,%9}, {%0,%1,%2,%3};"
                 : "+f"(c[0]), "+f"(c[1]), "+f"(c[2]), "+f"(c[3])
                 : "r"(a[0]), "r"(a[1]), "r"(a[2]), "r"(a[3]), "r"(b[0]), "r"(b[1]));
}

// ---------------- 1: degree histogram (1 thread/edge) ----------------
__global__ void k_hist(const int* __restrict__ dst) {
    int e = blockIdx.x * blockDim.x + threadIdx.x;
    if (e < N_EDGES) atomicAdd(&g_count[dst[e]], 1);
}

// ---------------- 2: exclusive scan (single block) + re-zero counts --------
__global__ void k_scan() {
    __shared__ int sh[10240];
    __shared__ int wsums[32];
    int tid = threadIdx.x, lane = tid & 31, w = tid >> 5;
    int4* sh4 = (int4*)sh;
    int4* gc4 = (int4*)g_count;
    for (int i = tid; i < 2560; i += 1024) sh4[i] = gc4[i];
    __syncthreads();
    // re-zero counts for next kernel_launch call (maintains zero invariant)
    const int4 z4 = make_int4(0, 0, 0, 0);
    for (int i = tid; i < 2560; i += 1024) gc4[i] = z4;
    int base = tid * 10;
    int local[10];
    int s = 0;
#pragma unroll
    for (int i = 0; i < 10; i++) { local[i] = s; s += sh[base + i]; }
    int inc = s;
#pragma unroll
    for (int off = 1; off < 32; off <<= 1) {
        int v = __shfl_up_sync(0xffffffffu, inc, off);
        if (lane >= off) inc += v;
    }
    if (lane == 31) wsums[w] = inc;
    __syncthreads();
    if (w == 0) {
        int v = wsums[lane];
        int wi = v;
#pragma unroll
        for (int off = 1; off < 32; off <<= 1) {
            int t = __shfl_up_sync(0xffffffffu, wi, off);
            if (lane >= off) wi += t;
        }
        wsums[lane] = wi - v;   // exclusive
    }
    __syncthreads();
    int excl = wsums[w] + inc - s;
#pragma unroll
    for (int i = 0; i < 10; i++) sh[base + i] = excl + local[i];
    __syncthreads();
    int4* rs4 = (int4*)g_rowstart;
    int4* wo4 = (int4*)g_woff;
    for (int i = tid; i < 2500; i += 1024) { int4 v = sh4[i]; rs4[i] = v; wo4[i] = v; }
    if (tid == 0) g_rowstart[N_NODES] = N_EDGES;
}

// ---------------- 3: scatter edges into CSR buckets (1 thread/edge) --------
__global__ void k_scatter(const int* __restrict__ src, const int* __restrict__ dst) {
    int e = blockIdx.x * blockDim.x + threadIdx.x;
    if (e < N_EDGES) {
        int p = atomicAdd(&g_woff[dst[e]], 1);
        g_srcs[p] = src[e];
    }
}

// ---------------- 4: tensor-core GEMM ft = feat @ W (+ fused el/er) --------
// block: 256 threads = 8 warps. Tile: 128 rows x 64 cols (one head). K = 256.
#define ASTRIDE 72
__global__ __launch_bounds__(256) void k_gemm(const float* __restrict__ A,
                                              const float* __restrict__ B,
                                              const float* __restrict__ al,
                                              const float* __restrict__ ar) {
    __shared__ __half As[128 * ASTRIDE];
    __shared__ __half Bs[64 * ASTRIDE];
    const int bx = blockIdx.x;          // head (0..7)
    const int by = blockIdx.y;          // row tile (0..78)
    const int tid = threadIdx.x;
    const int w = tid >> 5, lane = tid & 31;

    float acc[8][4];
#pragma unroll
    for (int i = 0; i < 8; i++)
#pragma unroll
        for (int j = 0; j < 4; j++) acc[i][j] = 0.f;

    const int arow = tid >> 1, apart = tid & 1;
    const int gm_l = by * 128 + arow;
    const bool aok = gm_l < N_NODES;
    const int bk = tid >> 2, bnq = (tid & 3) * 16;

    const unsigned s_as = (unsigned)__cvta_generic_to_shared(As);
    const unsigned s_bs = (unsigned)__cvta_generic_to_shared(Bs);
    const int r15 = lane & 15, c8 = (lane >> 4) * 8;
    const unsigned a_base = s_as + (unsigned)(((w * 16 + r15) * ASTRIDE + c8) * 2);
    const unsigned b_base = s_bs + (unsigned)((r15 * ASTRIDE + c8) * 2);

    for (int kc = 0; kc < 4; kc++) {      // K chunks of 64
        float4 av[8];
        const float* ap = A + (long long)gm_l * IN_F + kc * 64 + apart * 32;
#pragma unroll
        for (int j = 0; j < 8; j++)
            av[j] = aok ? *(const float4*)(ap + j * 4) : make_float4(0.f, 0.f, 0.f, 0.f);
        float4 bv[4];
        const float* bp = B + (long long)(kc * 64 + bk) * HD + bx * 64 + bnq;
#pragma unroll
        for (int j = 0; j < 4; j++) bv[j] = *(const float4*)(bp + j * 4);
        __syncthreads();
        __half* asr = &As[arow * ASTRIDE + apart * 32];
#pragma unroll
        for (int j = 0; j < 8; j++) {
            *(__half2*)(asr + j * 4)     = __floats2half2_rn(av[j].x, av[j].y);
            *(__half2*)(asr + j * 4 + 2) = __floats2half2_rn(av[j].z, av[j].w);
        }
        __half* bsr = &Bs[bk * ASTRIDE + bnq];
#pragma unroll
        for (int j = 0; j < 4; j++) {
            *(__half2*)(bsr + j * 4)     = __floats2half2_rn(bv[j].x, bv[j].y);
            *(__half2*)(bsr + j * 4 + 2) = __floats2half2_rn(bv[j].z, bv[j].w);
        }
        __syncthreads();
#pragma unroll
        for (int ks = 0; ks < 4; ks++) {
            unsigned af[4];
            ldsm_x4(af, a_base + ks * 32);
#pragma unroll
            for (int nb = 0; nb < 4; nb++) {
                unsigned bf[4];
                ldsm_x4t(bf, b_base + (unsigned)(ks * 16 * ASTRIDE * 2) + nb * 32);
                mma16816(acc[nb * 2],     af, bf);
                mma16816(acc[nb * 2 + 1], af, bf + 2);
            }
        }
    }

    // epilogue: fused el/er + fp16 ft store
    const int g = lane >> 2, tg = lane & 3;
    const int row0 = by * 128 + w * 16 + g;
    const int row1 = row0 + 8;
    float el0 = 0.f, er0 = 0.f, el1 = 0.f, er1 = 0.f;
#pragma unroll
    for (int na = 0; na < 8; na++) {
        int n = bx * 64 + na * 8 + tg * 2;
        float a0 = al[n], a1 = al[n + 1];
        float r0 = ar[n], r1 = ar[n + 1];
        el0 += acc[na][0] * a0 + acc[na][1] * a1;
        er0 += acc[na][0] * r0 + acc[na][1] * r1;
        el1 += acc[na][2] * a0 + acc[na][3] * a1;
        er1 += acc[na][2] * r0 + acc[na][3] * r1;
    }
#pragma unroll
    for (int off = 1; off <= 2; off <<= 1) {
        el0 += __shfl_xor_sync(0xffffffffu, el0, off);
        er0 += __shfl_xor_sync(0xffffffffu, er0, off);
        el1 += __shfl_xor_sync(0xffffffffu, el1, off);
        er1 += __shfl_xor_sync(0xffffffffu, er1, off);
    }
    if (row0 < N_NODES) {
        __half* fo = &g_fth[(long long)row0 * HD + bx * 64 + tg * 2];
#pragma unroll
        for (int na = 0; na < 8; na++)
            *(__half2*)(fo + na * 8) = __floats2half2_rn(acc[na][0], acc[na][1]);
        if (tg == 0) { g_el[row0 * NH + bx] = el0; g_er[row0 * NH + bx] = er0; }
    }
    if (row1 < N_NODES) {
        __half* fo = &g_fth[(long long)row1 * HD + bx * 64 + tg * 2];
#pragma unroll
        for (int na = 0; na < 8; na++)
            *(__half2*)(fo + na * 8) = __floats2half2_rn(acc[na][2], acc[na][3]);
        if (tg == 0) { g_el[row1 * NH + bx] = el1; g_er[row1 * NH + bx] = er1; }
    }
}

// ---------------- 5: softmax stats + normalized attention (warp per dst) ---
__global__ void k_soft(const float* __restrict__ adj, const int* __restrict__ idxp) {
    int d    = blockIdx.x * 8 + (threadIdx.x >> 5);
    int lane = threadIdx.x & 31;
    int s0 = g_rowstart[d], s1 = g_rowstart[d + 1];
    if (s1 <= s0) return;

    int idx = *idxp;
    int h   = lane & 7;
    int sub = lane >> 3;
    float er_h = g_er[d * NH + h];

    // online per-head max + expsum (strided across 4 sub-lanes)
    float m = -1e30f, ssum = 0.f;
    for (int j = s0 + sub; j < s1; j += 4) {
        int s = g_srcs[j];
        float e = g_el[s * NH + h] + er_h;
        e = e > 0.f ? e : 0.2f * e;
        if (e > m) { ssum *= __expf(m - e); m = e; }
        ssum += __expf(e - m);
    }
#pragma unroll
    for (int off = 8; off <= 16; off <<= 1) {
        float mo = __shfl_xor_sync(0xffffffffu, m, off);
        float so = __shfl_xor_sync(0xffffffffu, ssum, off);
        float mn = fmaxf(m, mo);
        ssum = ssum * __expf(m - mn) + so * __expf(mo - mn);
        m = mn;
    }
    float inv = __frcp_rn(ssum);

    const long long adjbase = (long long)idx * N_NODES + (long long)d + idx;
    for (int j = s0 + sub; j < s1; j += 4) {
        int s = g_srcs[j];
        float e = g_el[s * NH + h] + er_h;
        e = e > 0.f ? e : 0.2f * e;
        float wadj = __ldg(&adj[(long long)s * N_NODES + adjbase]);
        g_a[j * NH + h] = __expf(e - m) * inv * wadj;
    }
}

// ---------------- 6: aggregation (warp per dst, single lean pass) ----------
__global__ void k_agg(float* __restrict__ out) {
    int d    = blockIdx.x * 8 + (threadIdx.x >> 5);
    int lane = threadIdx.x & 31;
    int s0 = g_rowstart[d], s1 = g_rowstart[d + 1];

    float acc0[8], acc1[8];
#pragma unroll
    for (int t = 0; t < 8; t++) { acc0[t] = 0.f; acc1[t] = 0.f; }

    const int q0 = lane >> 3;        // head for fp16 chunk 0 (features lane*8..)
    const int q1 = 4 + (lane >> 3);  // head for fp16 chunk 1 (features 256+lane*8..)
#pragma unroll 4
    for (int j = s0; j < s1; j++) {
        int s = g_srcs[j];
        float a0 = __ldg(&g_a[j * NH + q0]);
        float a1 = __ldg(&g_a[j * NH + q1]);
        const uint4* fh = (const uint4*)&g_fth[(long long)s * HD];
        uint4 u0 = __ldg(&fh[lane]);
        uint4 u1 = __ldg(&fh[lane + 32]);
        {
            const __half2* hp = (const __half2*)&u0;
#pragma unroll
            for (int t = 0; t < 4; t++) {
                float2 f = __half22float2(hp[t]);
                acc0[2 * t]     += a0 * f.x;
                acc0[2 * t + 1] += a0 * f.y;
            }
        }
        {
            const __half2* hp = (const __half2*)&u1;
#pragma unroll
            for (int t = 0; t < 4; t++) {
                float2 f = __half22float2(hp[t]);
                acc1[2 * t]     += a1 * f.x;
                acc1[2 * t + 1] += a1 * f.y;
            }
        }
    }
    float* o = out + (long long)d * HD;
    *(float4*)&o[lane * 8]           = make_float4(acc0[0], acc0[1], acc0[2], acc0[3]);
    *(float4*)&o[lane * 8 + 4]       = make_float4(acc0[4], acc0[5], acc0[6], acc0[7]);
    *(float4*)&o[256 + lane * 8]     = make_float4(acc1[0], acc1[1], acc1[2], acc1[3]);
    *(float4*)&o[256 + lane * 8 + 4] = make_float4(acc1[4], acc1[5], acc1[6], acc1[7]);
}

// ---------------- streams for fork-join overlap (static init; no device mem)
static cudaStream_t g_s2;
static cudaEvent_t  g_evA, g_evB;
namespace {
struct StreamInit {
    StreamInit() {
        cudaStreamCreateWithFlags(&g_s2, cudaStreamNonBlocking);
        cudaEventCreateWithFlags(&g_evA, cudaEventDisableTiming);
        cudaEventCreateWithFlags(&g_evB, cudaEventDisableTiming);
    }
};
StreamInit s_streamInit;
}

// ---------------- launch ----------------
extern "C" void kernel_launch(void* const* d_in, const int* in_sizes, int n_in,
                              void* d_out, int out_size) {
    const float* feat = (const float*)d_in[0];
    const float* W    = (const float*)d_in[1];
    const float* al   = (const float*)d_in[2];
    const float* ar   = (const float*)d_in[3];
    const float* adj  = (const float*)d_in[4];
    const int*   src  = (const int*)d_in[5];
    const int*   dst  = (const int*)d_in[6];
    const int*   idxp = (const int*)d_in[7];
    float* out = (float*)d_out;

    // fork: CSR-build chain on g_s2, GEMM on capture (default) stream
    cudaEventRecord(g_evA, 0);
    cudaStreamWaitEvent(g_s2, g_evA, 0);

    k_hist<<<(N_EDGES + 255) / 256, 256, 0, g_s2>>>(dst);          // launch 1
    k_scan<<<1, 1024, 0, g_s2>>>();                                // launch 2
    k_scatter<<<(N_EDGES + 255) / 256, 256, 0, g_s2>>>(src, dst);  // launch 3
    cudaEventRecord(g_evB, g_s2);

    dim3 ggrid(NH, (N_NODES + 127) / 128);
    k_gemm<<<ggrid, 256>>>(feat, W, al, ar);                       // launch 4 (profiled)

    // join: soft needs CSR + el/er
    cudaStreamWaitEvent(0, g_evB, 0);
    k_soft<<<N_NODES / 8, 256>>>(adj, idxp);                       // launch 5
    k_agg<<<N_NODES / 8, 256>>>(out);                              // launch 6
}

// round 11
// speedup vs baseline: 2.2490x; 1.1862x over previous
#include <cuda_runtime.h>
#include <cuda_fp16.h>
#include <cstdint>

#define N_NODES 10000
#define N_EDGES 320000
#define IN_F    256
#define HD      512   // NUM_HEADS * OUT_FEATS
#define NH      8

// ---------------- scratch (device globals; zero-initialized at load) -------
__device__ __half g_ah[N_NODES * IN_F];     // feat in fp16
__device__ __half g_bh[IN_F * HD];          // W in fp16
__device__ __half g_fth[N_NODES * HD];      // projected features fp16 [N, 512]
__device__ float  g_el[N_NODES * NH];
__device__ float  g_er[N_NODES * NH];
__device__ int    g_count[10240];           // zeroed by k_scan after use
__device__ int    g_rowstart[N_NODES + 1];
__device__ int    g_woff[N_NODES];
__device__ int    g_srcs[N_EDGES];          // src indices bucketed by dst (CSR)
__device__ float  g_a[N_EDGES * NH];        // normalized attention (incl adj mask)

// ---------------- asm helpers ----------------
__device__ __forceinline__ void ldsm_x4(unsigned* r, unsigned addr) {
    asm volatile("ldmatrix.sync.aligned.m8n8.x4.shared.b16 {%0,%1,%2,%3}, [%4];"
                 : "=r"(r[0]), "=r"(r[1]), "=r"(r[2]), "=r"(r[3]) : "r"(addr));
}
__device__ __forceinline__ void ldsm_x4t(unsigned* r, unsigned addr) {
    asm volatile("ldmatrix.sync.aligned.m8n8.x4.trans.shared.b16 {%0,%1,%2,%3}, [%4];"
                 : "=r"(r[0]), "=r"(r[1]), "=r"(r[2]), "=r"(r[3]) : "r"(addr));
}
__device__ __forceinline__ void mma16816(float* c, const unsigned* a, const unsigned* b) {
    asm volatile("mma.sync.aligned.m16n8k16.row.col.f32.f16.f16.f32 "
                 "{%0,%1,%2,%3}, {%4,%5,%6,%7}, {%8,%9}, {%0,%1,%2,%3};"
                 : "+f"(c[0]), "+f"(c[1]), "+f"(c[2]), "+f"(c[3])
                 : "r"(a[0]), "r"(a[1]), "r"(a[2]), "r"(a[3]), "r"(b[0]), "r"(b[1]));
}
__device__ __forceinline__ void cp16(unsigned saddr, const void* gaddr, int src_bytes) {
    asm volatile("cp.async.cg.shared.global [%0], [%1], 16, %2;"
                 :: "r"(saddr), "l"(gaddr), "r"(src_bytes));
}
#define CP_COMMIT() asm volatile("cp.async.commit_group;" ::: "memory")
#define CP_WAIT1()  asm volatile("cp.async.wait_group 1;" ::: "memory")
#define CP_WAIT0()  asm volatile("cp.async.wait_group 0;" ::: "memory")

// ---------------- 0a: convert feat -> fp16 ----------------
__global__ void k_cvtA(const float4* __restrict__ in) {
    int i = blockIdx.x * blockDim.x + threadIdx.x;   // 8 floats per thread
    if (i < N_NODES * IN_F / 8) {
        float4 a = in[i * 2], b = in[i * 2 + 1];
        __half2 h0 = __floats2half2_rn(a.x, a.y), h1 = __floats2half2_rn(a.z, a.w);
        __half2 h2 = __floats2half2_rn(b.x, b.y), h3 = __floats2half2_rn(b.z, b.w);
        uint4 v = make_uint4(*(unsigned*)&h0, *(unsigned*)&h1,
                             *(unsigned*)&h2, *(unsigned*)&h3);
        ((uint4*)g_ah)[i] = v;
    }
}
// ---------------- 0b: convert W -> fp16 ----------------
__global__ void k_cvtW(const float4* __restrict__ in) {
    int i = blockIdx.x * blockDim.x + threadIdx.x;
    if (i < IN_F * HD / 8) {
        float4 a = in[i * 2], b = in[i * 2 + 1];
        __half2 h0 = __floats2half2_rn(a.x, a.y), h1 = __floats2half2_rn(a.z, a.w);
        __half2 h2 = __floats2half2_rn(b.x, b.y), h3 = __floats2half2_rn(b.z, b.w);
        uint4 v = make_uint4(*(unsigned*)&h0, *(unsigned*)&h1,
                             *(unsigned*)&h2, *(unsigned*)&h3);
        ((uint4*)g_bh)[i] = v;
    }
}

// ---------------- 1: degree histogram (1 thread/edge) ----------------
__global__ void k_hist(const int* __restrict__ dst) {
    int e = blockIdx.x * blockDim.x + threadIdx.x;
    if (e < N_EDGES) atomicAdd(&g_count[dst[e]], 1);
}

// ---------------- 2: exclusive scan (single block) + re-zero counts --------
__global__ void k_scan() {
    __shared__ int sh[10240];
    __shared__ int wsums[32];
    int tid = threadIdx.x, lane = tid & 31, w = tid >> 5;
    int4* sh4 = (int4*)sh;
    int4* gc4 = (int4*)g_count;
    for (int i = tid; i < 2560; i += 1024) sh4[i] = gc4[i];
    __syncthreads();
    const int4 z4 = make_int4(0, 0, 0, 0);
    for (int i = tid; i < 2560; i += 1024) gc4[i] = z4;
    int base = tid * 10;
    int local[10];
    int s = 0;
#pragma unroll
    for (int i = 0; i < 10; i++) { local[i] = s; s += sh[base + i]; }
    int inc = s;
#pragma unroll
    for (int off = 1; off < 32; off <<= 1) {
        int v = __shfl_up_sync(0xffffffffu, inc, off);
        if (lane >= off) inc += v;
    }
    if (lane == 31) wsums[w] = inc;
    __syncthreads();
    if (w == 0) {
        int v = wsums[lane];
        int wi = v;
#pragma unroll
        for (int off = 1; off < 32; off <<= 1) {
            int t = __shfl_up_sync(0xffffffffu, wi, off);
            if (lane >= off) wi += t;
        }
        wsums[lane] = wi - v;   // exclusive
    }
    __syncthreads();
    int excl = wsums[w] + inc - s;
#pragma unroll
    for (int i = 0; i < 10; i++) sh[base + i] = excl + local[i];
    __syncthreads();
    int4* rs4 = (int4*)g_rowstart;
    int4* wo4 = (int4*)g_woff;
    for (int i = tid; i < 2500; i += 1024) { int4 v = sh4[i]; rs4[i] = v; wo4[i] = v; }
    if (tid == 0) g_rowstart[N_NODES] = N_EDGES;
}

// ---------------- 3: scatter edges into CSR buckets (1 thread/edge) --------
__global__ void k_scatter(const int* __restrict__ src, const int* __restrict__ dst) {
    int e = blockIdx.x * blockDim.x + threadIdx.x;
    if (e < N_EDGES) {
        int p = atomicAdd(&g_woff[dst[e]], 1);
        g_srcs[p] = src[e];
    }
}

// ---------------- 4: tensor-core GEMM, cp.async staged, B resident --------
// block: 256 thr = 8 warps. Tile 128 rows x 64 cols (one head). K=256.
// smem: Bs = full 256x64 head tile (loaded once), As = 2 x (128x64) k-slices.
#define ASTRIDE 72
#define B_BYTES (256 * ASTRIDE * 2)     // 36864
#define A_BYTES (128 * ASTRIDE * 2)     // 18432
#define GEMM_SMEM (B_BYTES + 2 * A_BYTES)
__global__ __launch_bounds__(256) void k_gemm(const float* __restrict__ al,
                                              const float* __restrict__ ar) {
    extern __shared__ __half dynsmem[];
    const int bx = blockIdx.x;          // head (0..7)
    const int by = blockIdx.y;          // row tile (0..78)
    const int tid = threadIdx.x;
    const int w = tid >> 5, lane = tid & 31;
    const int row0 = by * 128;

    const unsigned s_b  = (unsigned)__cvta_generic_to_shared(dynsmem);
    const unsigned s_a0 = s_b + B_BYTES;

    // --- issue B (whole head tile, 2048 16B chunks) ---
#pragma unroll
    for (int i = 0; i < 8; i++) {
        int idx = tid + i * 256;
        int k = idx >> 3, c = idx & 7;
        cp16(s_b + k * (ASTRIDE * 2) + c * 16, g_bh + k * HD + bx * 64 + c * 8, 16);
    }
    // --- issue A slice kc=0 ---
#pragma unroll
    for (int i = 0; i < 4; i++) {
        int idx = tid + i * 256;
        int r = idx >> 3, c = idx & 7;
        int grow = row0 + r;
        int ok = grow < N_NODES ? 16 : 0;
        int gsafe = grow < N_NODES ? grow : (N_NODES - 1);
        cp16(s_a0 + r * (ASTRIDE * 2) + c * 16,
             g_ah + (size_t)gsafe * IN_F + c * 8, ok);
    }
    CP_COMMIT();   // group 0: B + A0
#pragma unroll
    for (int i = 0; i < 4; i++) {
        int idx = tid + i * 256;
        int r = idx >> 3, c = idx & 7;
        int grow = row0 + r;
        int ok = grow < N_NODES ? 16 : 0;
        int gsafe = grow < N_NODES ? grow : (N_NODES - 1);
        cp16(s_a0 + A_BYTES + r * (ASTRIDE * 2) + c * 16,
             g_ah + (size_t)gsafe * IN_F + 64 + c * 8, ok);
    }
    CP_COMMIT();   // group 1: A1

    float acc[8][4];
#pragma unroll
    for (int i = 0; i < 8; i++)
#pragma unroll
        for (int j = 0; j < 4; j++) acc[i][j] = 0.f;

    const int r15 = lane & 15, c8 = (lane >> 4) * 8;

#pragma unroll
    for (int kc = 0; kc < 4; kc++) {
        if (kc < 3) { CP_WAIT1(); } else { CP_WAIT0(); }
        __syncthreads();
        const unsigned a_base = s_a0 + (kc & 1) * A_BYTES
                              + (unsigned)(((w * 16 + r15) * ASTRIDE + c8) * 2);
        const unsigned b_base = s_b + (unsigned)(((kc * 64 + r15) * ASTRIDE + c8) * 2);
#pragma unroll
        for (int ks = 0; ks < 4; ks++) {
            unsigned af[4];
            ldsm_x4(af, a_base + ks * 32);
#pragma unroll
            for (int nb = 0; nb < 4; nb++) {
                unsigned bf[4];
                ldsm_x4t(bf, b_base + (unsigned)(ks * 16 * ASTRIDE * 2) + nb * 32);
                mma16816(acc[nb * 2],     af, bf);
                mma16816(acc[nb * 2 + 1], af, bf + 2);
            }
        }
        if (kc < 2) {
            __syncthreads();   // all warps done reading buf (kc&1) before overwrite
#pragma unroll
            for (int i = 0; i < 4; i++) {
                int idx = tid + i * 256;
                int r = idx >> 3, c = idx & 7;
                int grow = row0 + r;
                int ok = grow < N_NODES ? 16 : 0;
                int gsafe = grow < N_NODES ? grow : (N_NODES - 1);
                cp16(s_a0 + (kc & 1) * A_BYTES + r * (ASTRIDE * 2) + c * 16,
                     g_ah + (size_t)gsafe * IN_F + (kc + 2) * 64 + c * 8, ok);
            }
            CP_COMMIT();
        }
    }

    // epilogue: fused el/er + fp16 ft store
    const int g = lane >> 2, tg = lane & 3;
    const int rr0 = row0 + w * 16 + g;
    const int rr1 = rr0 + 8;
    float el0 = 0.f, er0 = 0.f, el1 = 0.f, er1 = 0.f;
#pragma unroll
    for (int na = 0; na < 8; na++) {
        int n = bx * 64 + na * 8 + tg * 2;
        float a0 = al[n], a1 = al[n + 1];
        float r0 = ar[n], r1 = ar[n + 1];
        el0 += acc[na][0] * a0 + acc[na][1] * a1;
        er0 += acc[na][0] * r0 + acc[na][1] * r1;
        el1 += acc[na][2] * a0 + acc[na][3] * a1;
        er1 += acc[na][2] * r0 + acc[na][3] * r1;
    }
#pragma unroll
    for (int off = 1; off <= 2; off <<= 1) {
        el0 += __shfl_xor_sync(0xffffffffu, el0, off);
        er0 += __shfl_xor_sync(0xffffffffu, er0, off);
        el1 += __shfl_xor_sync(0xffffffffu, el1, off);
        er1 += __shfl_xor_sync(0xffffffffu, er1, off);
    }
    if (rr0 < N_NODES) {
        __half* fo = &g_fth[(long long)rr0 * HD + bx * 64 + tg * 2];
#pragma unroll
        for (int na = 0; na < 8; na++)
            *(__half2*)(fo + na * 8) = __floats2half2_rn(acc[na][0], acc[na][1]);
        if (tg == 0) { g_el[rr0 * NH + bx] = el0; g_er[rr0 * NH + bx] = er0; }
    }
    if (rr1 < N_NODES) {
        __half* fo = &g_fth[(long long)rr1 * HD + bx * 64 + tg * 2];
#pragma unroll
        for (int na = 0; na < 8; na++)
            *(__half2*)(fo + na * 8) = __floats2half2_rn(acc[na][2], acc[na][3]);
        if (tg == 0) { g_el[rr1 * NH + bx] = el1; g_er[rr1 * NH + bx] = er1; }
    }
}

// ---------------- 5: softmax stats + normalized attention (warp per dst) ---
__global__ void k_soft(const float* __restrict__ adj, const int* __restrict__ idxp) {
    int d    = blockIdx.x * 8 + (threadIdx.x >> 5);
    int lane = threadIdx.x & 31;
    int s0 = g_rowstart[d], s1 = g_rowstart[d + 1];
    if (s1 <= s0) return;

    int idx = *idxp;
    int h   = lane & 7;
    int sub = lane >> 3;
    float er_h = g_er[d * NH + h];

    float m = -1e30f, ssum = 0.f;
    for (int j = s0 + sub; j < s1; j += 4) {
        int s = g_srcs[j];
        float e = g_el[s * NH + h] + er_h;
        e = e > 0.f ? e : 0.2f * e;
        if (e > m) { ssum *= __expf(m - e); m = e; }
        ssum += __expf(e - m);
    }
#pragma unroll
    for (int off = 8; off <= 16; off <<= 1) {
        float mo = __shfl_xor_sync(0xffffffffu, m, off);
        float so = __shfl_xor_sync(0xffffffffu, ssum, off);
        float mn = fmaxf(m, mo);
        ssum = ssum * __expf(m - mn) + so * __expf(mo - mn);
        m = mn;
    }
    float inv = __frcp_rn(ssum);

    const long long adjbase = (long long)idx * N_NODES + (long long)d + idx;
    for (int j = s0 + sub; j < s1; j += 4) {
        int s = g_srcs[j];
        float e = g_el[s * NH + h] + er_h;
        e = e > 0.f ? e : 0.2f * e;
        float wadj = __ldg(&adj[(long long)s * N_NODES + adjbase]);
        g_a[j * NH + h] = __expf(e - m) * inv * wadj;
    }
}

// ---------------- 6: aggregation (warp per dst, single lean pass) ----------
__global__ void k_agg(float* __restrict__ out) {
    int d    = blockIdx.x * 8 + (threadIdx.x >> 5);
    int lane = threadIdx.x & 31;
    int s0 = g_rowstart[d], s1 = g_rowstart[d + 1];

    float acc0[8], acc1[8];
#pragma unroll
    for (int t = 0; t < 8; t++) { acc0[t] = 0.f; acc1[t] = 0.f; }

    const int q0 = lane >> 3;
    const int q1 = 4 + (lane >> 3);
#pragma unroll 4
    for (int j = s0; j < s1; j++) {
        int s = g_srcs[j];
        float a0 = __ldg(&g_a[j * NH + q0]);
        float a1 = __ldg(&g_a[j * NH + q1]);
        const uint4* fh = (const uint4*)&g_fth[(long long)s * HD];
        uint4 u0 = __ldg(&fh[lane]);
        uint4 u1 = __ldg(&fh[lane + 32]);
        {
            const __half2* hp = (const __half2*)&u0;
#pragma unroll
            for (int t = 0; t < 4; t++) {
                float2 f = __half22float2(hp[t]);
                acc0[2 * t]     += a0 * f.x;
                acc0[2 * t + 1] += a0 * f.y;
            }
        }
        {
            const __half2* hp = (const __half2*)&u1;
#pragma unroll
            for (int t = 0; t < 4; t++) {
                float2 f = __half22float2(hp[t]);
                acc1[2 * t]     += a1 * f.x;
                acc1[2 * t + 1] += a1 * f.y;
            }
        }
    }
    float* o = out + (long long)d * HD;
    *(float4*)&o[lane * 8]           = make_float4(acc0[0], acc0[1], acc0[2], acc0[3]);
    *(float4*)&o[lane * 8 + 4]       = make_float4(acc0[4], acc0[5], acc0[6], acc0[7]);
    *(float4*)&o[256 + lane * 8]     = make_float4(acc1[0], acc1[1], acc1[2], acc1[3]);
    *(float4*)&o[256 + lane * 8 + 4] = make_float4(acc1[4], acc1[5], acc1[6], acc1[7]);
}

// ---------------- streams + gemm smem attr (static init; no device mem) ----
static cudaStream_t g_s2;
static cudaEvent_t  g_evA, g_evB;
namespace {
struct StreamInit {
    StreamInit() {
        cudaStreamCreateWithFlags(&g_s2, cudaStreamNonBlocking);
        cudaEventCreateWithFlags(&g_evA, cudaEventDisableTiming);
        cudaEventCreateWithFlags(&g_evB, cudaEventDisableTiming);
        cudaFuncSetAttribute(k_gemm, cudaFuncAttributeMaxDynamicSharedMemorySize,
                             GEMM_SMEM);
    }
};
StreamInit s_streamInit;
}

// ---------------- launch ----------------
extern "C" void kernel_launch(void* const* d_in, const int* in_sizes, int n_in,
                              void* d_out, int out_size) {
    const float* feat = (const float*)d_in[0];
    const float* W    = (const float*)d_in[1];
    const float* al   = (const float*)d_in[2];
    const float* ar   = (const float*)d_in[3];
    const float* adj  = (const float*)d_in[4];
    const int*   src  = (const int*)d_in[5];
    const int*   dst  = (const int*)d_in[6];
    const int*   idxp = (const int*)d_in[7];
    float* out = (float*)d_out;

    // fork: CSR-build chain on g_s2; convert + GEMM on capture stream
    cudaEventRecord(g_evA, 0);
    cudaStreamWaitEvent(g_s2, g_evA, 0);

    k_cvtA<<<1250, 256>>>((const float4*)feat);                    // launch 1
    k_cvtW<<<64, 256>>>((const float4*)W);                         // launch 2
    k_hist<<<(N_EDGES + 255) / 256, 256, 0, g_s2>>>(dst);          // launch 3
    dim3 ggrid(NH, (N_NODES + 127) / 128);
    k_gemm<<<ggrid, 256, GEMM_SMEM>>>(al, ar);                     // launch 4 (profiled)
    k_scan<<<1, 1024, 0, g_s2>>>();                                // launch 5
    k_scatter<<<(N_EDGES + 255) / 256, 256, 0, g_s2>>>(src, dst);  // launch 6
    cudaEventRecord(g_evB, g_s2);

    // join: soft needs CSR + el/er
    cudaStreamWaitEvent(0, g_evB, 0);
    k_soft<<<N_NODES / 8, 256>>>(adj, idxp);                       // launch 7
    k_agg<<<N_NODES / 8, 256>>>(out);                              // launch 8
}